// round 12
// baseline (speedup 1.0000x reference)
#include <cuda_runtime.h>
#include <cuda_fp16.h>

#define NN  1024
#define RAW 128
#define DD  128
#define HH  256

#define SELU_ALPHA 1.6732632423543772f
#define SELU_SCALE 1.0507009873554805f

typedef unsigned long long ull;

// Scratch (static __device__ arrays; no allocation)
__device__ __half  g_Ah  [HH * NN];   // A^T fp16                 [k][j]
__device__ __half  g_EAh [HH * NN];   // exp(A^T) fp16            [k][j]
__device__ __half2 g_Bdh [HH * NN];   // {B,B} dup fp16           [k][i]
__device__ __half2 g_EBdh[HH * NN];   // {expB,expB} dup fp16     [k][i]
__device__ float   g_P   [NN];        // P[j] = sum_k hw_k A[k][j]
__device__ float   g_Q   [NN];        // Q[i] = sum_k hw_k B[k][i]
__device__ __half2 g_wh  [HH * 2];    // [k][0]={hw,hw} [k][1]={asw,asw}
__device__ float   g_c0;              // b2 - sum asw

// ---------------------------------------------------------------------------
// Fused aux (unchanged from R11): prep + z + A/B GEMMs + exp + transposed
// fp16 stores + P/Q rank-1 terms.  256 blocks x 256 threads.
// ---------------------------------------------------------------------------
__global__ __launch_bounds__(256) void aux_kernel(
        const float* __restrict__ x,     const float* __restrict__ W_enc,
        const float* __restrict__ b_enc, const float* __restrict__ W1,
        const float* __restrict__ b1,    const float* __restrict__ W2,
        const float* __restrict__ b2) {
    __shared__ float sx [4][RAW];
    __shared__ float sz [4][DD];
    __shared__ float swa[16 * 256];
    __shared__ float swb[16 * 256];
    __shared__ float stV[HH * 5];
    __shared__ float stE[HH * 5];
    __shared__ float redR[8][4];

    const int t  = threadIdx.x;          // k in [0,256)
    const int j0 = blockIdx.x * 4;

    if (blockIdx.x == 0) {
        float w   = W2[t];
        float sw  = SELU_SCALE * w;
        float asw = SELU_ALPHA * sw;
        // round hw through fp16 so the relu-cancellation with P/Q is exact
        float hwr = __half2float(__float2half(0.5f * sw));
        g_wh[2 * t]     = __float2half2_rn(hwr);
        g_wh[2 * t + 1] = __float2half2_rn(asw);
        stV[t] = asw;
        __syncthreads();
        #pragma unroll
        for (int s = 128; s > 0; s >>= 1) {
            if (t < s) stV[t] += stV[t + s];
            __syncthreads();
        }
        if (t == 0) g_c0 = b2[0] - stV[0];
        __syncthreads();
    }

    #pragma unroll
    for (int s = 0; s < 2; s++) {
        int idx = t + s * 256;
        sx[idx >> 7][idx & 127] = x[(j0 + (idx >> 7)) * RAW + (idx & 127)];
    }
    __syncthreads();

    {
        const int k  = t & 127;
        const int rh = t >> 7;
        float za0 = 0.f, za1 = 0.f;
        for (int c0 = 0; c0 < RAW; c0 += 16) {
            const float4* src = reinterpret_cast<const float4*>(W_enc + c0 * DD);
            float4* dst = reinterpret_cast<float4*>(swa);
            dst[t]       = src[t];
            dst[t + 256] = src[t + 256];
            __syncthreads();
            #pragma unroll
            for (int cc = 0; cc < 16; cc++) {
                float w = swa[cc * DD + k];
                za0 = fmaf(sx[2 * rh][c0 + cc],     w, za0);
                za1 = fmaf(sx[2 * rh + 1][c0 + cc], w, za1);
            }
            __syncthreads();
        }
        float bb = b_enc[k];
        sz[2 * rh][k]     = za0 + bb;
        sz[2 * rh + 1][k] = za1 + bb;
    }
    __syncthreads();

    float accA[4] = {0.f, 0.f, 0.f, 0.f};
    float accB[4] = {0.f, 0.f, 0.f, 0.f};
    for (int c0 = 0; c0 < DD; c0 += 16) {
        const float4* srcA = reinterpret_cast<const float4*>(W1 + c0 * HH);
        const float4* srcB = reinterpret_cast<const float4*>(W1 + (c0 + DD) * HH);
        float4* dstA = reinterpret_cast<float4*>(swa);
        float4* dstB = reinterpret_cast<float4*>(swb);
        #pragma unroll
        for (int s = 0; s < 4; s++) {
            dstA[t + s * 256] = srcA[t + s * 256];
            dstB[t + s * 256] = srcB[t + s * 256];
        }
        __syncthreads();
        #pragma unroll
        for (int cc = 0; cc < 16; cc++) {
            float wa = swa[cc * HH + t];
            float wb = swb[cc * HH + t];
            #pragma unroll
            for (int r = 0; r < 4; r++) {
                float zz = sz[r][c0 + cc];
                accA[r] = fmaf(zz, wa, accA[r]);
                accB[r] = fmaf(zz, wb, accB[r]);
            }
        }
        __syncthreads();
    }

    const float b1k = b1[t];
    const float hw  = __half2float(__float2half(0.5f * SELU_SCALE * W2[t]));
    const int wid = t >> 5, lid = t & 31;

    // ---- round A: Ah/EAh fp16 stores + P ----
    {
        float pv[4];
        #pragma unroll
        for (int r = 0; r < 4; r++) {
            float a = accA[r] + b1k;
            stV[t * 5 + r] = a;
            stE[t * 5 + r] = __expf(fminf(fmaxf(a, -8.f), 8.f));
            pv[r] = hw * a;
        }
        #pragma unroll
        for (int r = 0; r < 4; r++) {
            float v = pv[r];
            #pragma unroll
            for (int s = 16; s > 0; s >>= 1)
                v += __shfl_down_sync(0xffffffffu, v, s);
            if (lid == 0) redR[wid][r] = v;
        }
        __syncthreads();
        #pragma unroll
        for (int p = 0; p < 4; p++) {
            int idx = p * 256 + t;
            int k = idx >> 2, j = idx & 3;
            g_Ah [k * NN + j0 + j] = __float2half(stV[k * 5 + j]);
            g_EAh[k * NN + j0 + j] = __float2half(stE[k * 5 + j]);
        }
        if (t < 4) {
            float s = 0.f;
            #pragma unroll
            for (int w2i = 0; w2i < 8; w2i++) s += redR[w2i][t];
            g_P[j0 + t] = s;
        }
        __syncthreads();
    }

    // ---- round B: Bdh/EBdh dup fp16 stores + Q ----
    {
        float pv[4];
        #pragma unroll
        for (int r = 0; r < 4; r++) {
            float b = accB[r];
            stV[t * 5 + r] = b;
            stE[t * 5 + r] = __expf(fminf(fmaxf(b, -8.f), 8.f));
            pv[r] = hw * b;
        }
        #pragma unroll
        for (int r = 0; r < 4; r++) {
            float v = pv[r];
            #pragma unroll
            for (int s = 16; s > 0; s >>= 1)
                v += __shfl_down_sync(0xffffffffu, v, s);
            if (lid == 0) redR[wid][r] = v;
        }
        __syncthreads();
        #pragma unroll
        for (int p = 0; p < 4; p++) {
            int idx = p * 256 + t;
            int k = idx >> 2, j = idx & 3;
            __half hb = __float2half(stV[k * 5 + j]);
            __half he = __float2half(stE[k * 5 + j]);
            g_Bdh [k * NN + j0 + j] = __halves2half2(hb, hb);
            g_EBdh[k * NN + j0 + j] = __halves2half2(he, he);
        }
        if (t < 4) {
            float s = 0.f;
            #pragma unroll
            for (int w2i = 0; w2i < 8; w2i++) s += redR[w2i][t];
            g_Q[j0 + t] = s;
        }
    }
}

// ---------------------------------------------------------------------------
// Main: o[i,j] = hsig( P[j] + Q[i] + c0 + sum_k [ hw_k*|v| + asw_k*sat(e) ] )
//   v = A[k][j]+B[k][i] (fp16), e = EA*EB with .sat == min(e,1) (inf-safe).
// 64x64 tiles, 256 thr, 4x4/thread, register prefetch.
// Core per 2 elements: HADD2 / AND-abs (ALU pipe) / HFMA2 / HMUL2.SAT /
// HFMA2  -> 4 fma-pipe ops + 1 alu op.  Single fp16 accumulator per pair,
// flushed to fp32 every 8 k.
// ---------------------------------------------------------------------------
__global__ __launch_bounds__(256, 2) void main_kernel(float* __restrict__ out) {
    __shared__ uint2   s_a  [16][16];   // [k][j4]  4 halves
    __shared__ uint2   s_ea [16][16];
    __shared__ uint4   s_bd [16][16];   // [k][i4]  4 dup half2
    __shared__ uint4   s_ebd[16][16];
    __shared__ uint2   s_w  [16];       // {hw2, aw2}

    const int tid = threadIdx.x;
    const int tx  = tid & 15;    // j quad
    const int ty  = tid >> 4;    // i quad
    const int j0  = blockIdx.x * 64;
    const int i0  = blockIdx.y * 64;

    const uint2* Ah2  = reinterpret_cast<const uint2*>(g_Ah);
    const uint2* EAh2 = reinterpret_cast<const uint2*>(g_EAh);
    const uint4* Bd4  = reinterpret_cast<const uint4*>(g_Bdh);
    const uint4* EBd4 = reinterpret_cast<const uint4*>(g_EBdh);
    const uint2* Wh2  = reinterpret_cast<const uint2*>(g_wh);

    const int ar = tid >> 4, ac = tid & 15;   // loader coords

    const int gja = ar * (NN / 4) + (j0 >> 2) + ac;   // uint2 index (4 halves)
    const int gib = ar * (NN / 4) + (i0 >> 2) + ac;   // uint4 index (4 half2)

    float accF[4][4];
    #pragma unroll
    for (int i = 0; i < 4; i++)
        #pragma unroll
        for (int j = 0; j < 4; j++) accF[i][j] = 0.f;

    // prefetch chunk 0
    uint2 pa, pea, pw;
    uint4 pb, peb;
    pa  = Ah2 [gja];
    pea = EAh2[gja];
    pb  = Bd4 [gib];
    peb = EBd4[gib];
    if (tid < 16) pw = Wh2[tid];

    for (int c = 0; c < 16; c++) {
        __syncthreads();
        s_a  [ar][ac] = pa;
        s_ea [ar][ac] = pea;
        s_bd [ar][ac] = pb;
        s_ebd[ar][ac] = peb;
        if (tid < 16) s_w[tid] = pw;
        __syncthreads();

        if (c < 15) {
            int oa = (c + 1) * 16 * (NN / 4);
            pa  = Ah2 [gja + oa];
            pea = EAh2[gja + oa];
            pb  = Bd4 [gib + oa];
            peb = EBd4[gib + oa];
            if (tid < 16) pw = Wh2[(c + 1) * 16 + tid];
        }

        #pragma unroll
        for (int h = 0; h < 2; h++) {
            __half2 acc[4][2];
            #pragma unroll
            for (int i = 0; i < 4; i++)
                #pragma unroll
                for (int jp = 0; jp < 2; jp++)
                    acc[i][jp] = __float2half2_rn(0.f);

            #pragma unroll
            for (int k8 = 0; k8 < 8; k8++) {
                const int kk = h * 8 + k8;
                uint2 ua  = s_a  [kk][tx];
                uint2 uea = s_ea [kk][tx];
                uint4 ub  = s_bd [kk][ty];
                uint4 ueb = s_ebd[kk][ty];
                uint2 uw  = s_w  [kk];

                unsigned au [2] = {ua.x, ua.y};
                unsigned eau[2] = {uea.x, uea.y};
                unsigned bu [4] = {ub.x, ub.y, ub.z, ub.w};
                unsigned ebu[4] = {ueb.x, ueb.y, ueb.z, ueb.w};
                __half2 hw2 = *reinterpret_cast<__half2*>(&uw.x);
                __half2 aw2 = *reinterpret_cast<__half2*>(&uw.y);

                #pragma unroll
                for (int i = 0; i < 4; i++) {
                    #pragma unroll
                    for (int jp = 0; jp < 2; jp++) {
                        // v = a + b (fp16x2)
                        __half2 v = __hadd2(*reinterpret_cast<__half2*>(&au[jp]),
                                            *reinterpret_cast<__half2*>(&bu[i]));
                        // |v| via integer AND on the ALU pipe
                        unsigned vu = *reinterpret_cast<unsigned*>(&v) & 0x7FFF7FFFu;
                        __half2 av = *reinterpret_cast<__half2*>(&vu);
                        acc[i][jp] = __hfma2(av, hw2, acc[i][jp]);
                        // e = sat(ea*eb) == min(exp(v), 1)
                        __half2 e = __hmul2_sat(*reinterpret_cast<__half2*>(&eau[jp]),
                                                *reinterpret_cast<__half2*>(&ebu[i]));
                        acc[i][jp] = __hfma2(e, aw2, acc[i][jp]);
                    }
                }
            }

            // flush fp16 partials to fp32
            #pragma unroll
            for (int i = 0; i < 4; i++) {
                #pragma unroll
                for (int jp = 0; jp < 2; jp++) {
                    float2 f = __half22float2(acc[i][jp]);
                    accF[i][2 * jp]     += f.x;
                    accF[i][2 * jp + 1] += f.y;
                }
            }
        }
    }

    // epilogue: + P[j] + Q[i] + c0, hard_sigmoid
    const float c0 = g_c0;
    float4 Pv = *reinterpret_cast<const float4*>(&g_P[j0 + tx * 4]);
    #pragma unroll
    for (int i = 0; i < 4; i++) {
        int   irow = i0 + ty * 4 + i;
        float base = g_Q[irow] + c0 + 3.0f;
        float4 o;
        o.x = fminf(fmaxf(accF[i][0] + Pv.x + base, 0.f), 6.f) * (1.f / 6.f);
        o.y = fminf(fmaxf(accF[i][1] + Pv.y + base, 0.f), 6.f) * (1.f / 6.f);
        o.z = fminf(fmaxf(accF[i][2] + Pv.z + base, 0.f), 6.f) * (1.f / 6.f);
        o.w = fminf(fmaxf(accF[i][3] + Pv.w + base, 0.f), 6.f) * (1.f / 6.f);
        *reinterpret_cast<float4*>(&out[irow * NN + j0 + tx * 4]) = o;
    }
}

// ---------------------------------------------------------------------------
extern "C" void kernel_launch(void* const* d_in, const int* in_sizes, int n_in,
                              void* d_out, int out_size) {
    const float* x     = (const float*)d_in[0];
    const float* W_enc = (const float*)d_in[1];
    const float* b_enc = (const float*)d_in[2];
    const float* W1    = (const float*)d_in[3];
    const float* b1    = (const float*)d_in[4];
    const float* W2    = (const float*)d_in[5];
    const float* b2    = (const float*)d_in[6];
    float* out = (float*)d_out;

    aux_kernel<<<NN / 4, 256>>>(x, W_enc, b_enc, W1, b1, W2, b2);

    dim3 grid(NN / 64, NN / 64);
    main_kernel<<<grid, 256>>>(out);
}

// round 13
// speedup vs baseline: 1.0111x; 1.0111x over previous
#include <cuda_runtime.h>
#include <cuda_fp16.h>

#define NN  1024
#define RAW 128
#define DD  128
#define HH  256

#define SELU_ALPHA 1.6732632423543772f
#define SELU_SCALE 1.0507009873554805f

// Scratch (static __device__ arrays; no allocation)
__device__ __half  g_Ah  [HH * NN];   // A^T fp16                 [k][j]
__device__ __half  g_EAh [HH * NN];   // exp(A^T) fp16            [k][j]
__device__ __half2 g_Bdh [HH * NN];   // {B,B} dup fp16           [k][i]
__device__ __half2 g_EBdh[HH * NN];   // {expB,expB} dup fp16     [k][i]
__device__ float   g_P   [NN];        // P[j] = sum_k hw_k A[k][j]
__device__ float   g_Q   [NN];        // Q[i] = sum_k hw_k B[k][i]
__device__ __half2 g_wh  [HH * 2];    // [k][0]={hw,hw} [k][1]={asw,asw}
__device__ float   g_c0;              // b2 - sum asw

// Grid barrier state (monotonic; replay-safe, never reset)
__device__ unsigned g_bar;
__device__ unsigned g_flag;

// Shared-memory overlay for the two phases
struct AuxSmem {
    float sx [4][RAW];
    float sz [4][DD];
    float swa[16 * 256];
    float swb[16 * 256];
    float stV[HH * 5];
    float stE[HH * 5];
    float redR[8][4];
};
struct MainSmem {
    uint2 a  [2][16][16];   // [buf][k][j4]  4 halves
    uint2 ea [2][16][16];
    uint4 bd [2][16][16];   // [buf][k][i4]  4 dup half2
    uint4 ebd[2][16][16];
    uint2 w  [2][16];       // {hw2, aw2}
};
union USmem { AuxSmem x; MainSmem m; };

// ---------------------------------------------------------------------------
// Fused kernel.  Grid (16,16) x 256 threads, occupancy 2 (all CTAs resident).
// Phase 1 (aux): CTA bid handles j rows [bid*4, bid*4+4): z, A/B GEMMs, exp,
//   transposed fp16 stores, P/Q.  Phase 2 (main): 64x64 output tile.
// ---------------------------------------------------------------------------
__global__ __launch_bounds__(256, 2) void fused_kernel(
        const float* __restrict__ x,     const float* __restrict__ W_enc,
        const float* __restrict__ b_enc, const float* __restrict__ W1,
        const float* __restrict__ b1,    const float* __restrict__ W2,
        const float* __restrict__ b2,    float* __restrict__ out) {
    __shared__ USmem sm;

    const int t   = threadIdx.x;
    const int bid = blockIdx.y * 16 + blockIdx.x;

    // ======================= PHASE 1: aux =======================
    {
        const int j0 = bid * 4;

        if (bid == 0) {
            float w   = W2[t];
            float sw  = SELU_SCALE * w;
            float asw = SELU_ALPHA * sw;
            float hwr = __half2float(__float2half(0.5f * sw));   // fp16-rounded
            g_wh[2 * t]     = __float2half2_rn(hwr);
            g_wh[2 * t + 1] = __float2half2_rn(asw);
            sm.x.stV[t] = asw;
            __syncthreads();
            #pragma unroll
            for (int s = 128; s > 0; s >>= 1) {
                if (t < s) sm.x.stV[t] += sm.x.stV[t + s];
                __syncthreads();
            }
            if (t == 0) g_c0 = b2[0] - sm.x.stV[0];
            __syncthreads();
        }

        #pragma unroll
        for (int s = 0; s < 2; s++) {
            int idx = t + s * 256;
            sm.x.sx[idx >> 7][idx & 127] = x[(j0 + (idx >> 7)) * RAW + (idx & 127)];
        }
        __syncthreads();

        // z = x @ W_enc + b_enc
        {
            const int k  = t & 127;
            const int rh = t >> 7;
            float za0 = 0.f, za1 = 0.f;
            for (int c0 = 0; c0 < RAW; c0 += 16) {
                const float4* src = reinterpret_cast<const float4*>(W_enc + c0 * DD);
                float4* dst = reinterpret_cast<float4*>(sm.x.swa);
                dst[t]       = src[t];
                dst[t + 256] = src[t + 256];
                __syncthreads();
                #pragma unroll
                for (int cc = 0; cc < 16; cc++) {
                    float w = sm.x.swa[cc * DD + k];
                    za0 = fmaf(sm.x.sx[2 * rh][c0 + cc],     w, za0);
                    za1 = fmaf(sm.x.sx[2 * rh + 1][c0 + cc], w, za1);
                }
                __syncthreads();
            }
            float bb = b_enc[k];
            sm.x.sz[2 * rh][k]     = za0 + bb;
            sm.x.sz[2 * rh + 1][k] = za1 + bb;
        }
        __syncthreads();

        // A = z@W1[:d]+b1 ; B = z@W1[d:]
        float accA[4] = {0.f, 0.f, 0.f, 0.f};
        float accB[4] = {0.f, 0.f, 0.f, 0.f};
        for (int c0 = 0; c0 < DD; c0 += 16) {
            const float4* srcA = reinterpret_cast<const float4*>(W1 + c0 * HH);
            const float4* srcB = reinterpret_cast<const float4*>(W1 + (c0 + DD) * HH);
            float4* dstA = reinterpret_cast<float4*>(sm.x.swa);
            float4* dstB = reinterpret_cast<float4*>(sm.x.swb);
            #pragma unroll
            for (int s = 0; s < 4; s++) {
                dstA[t + s * 256] = srcA[t + s * 256];
                dstB[t + s * 256] = srcB[t + s * 256];
            }
            __syncthreads();
            #pragma unroll
            for (int cc = 0; cc < 16; cc++) {
                float wa = sm.x.swa[cc * HH + t];
                float wb = sm.x.swb[cc * HH + t];
                #pragma unroll
                for (int r = 0; r < 4; r++) {
                    float zz = sm.x.sz[r][c0 + cc];
                    accA[r] = fmaf(zz, wa, accA[r]);
                    accB[r] = fmaf(zz, wb, accB[r]);
                }
            }
            __syncthreads();
        }

        const float b1k = b1[t];
        const float hw  = __half2float(__float2half(0.5f * SELU_SCALE * W2[t]));
        const int wid = t >> 5, lid = t & 31;

        // round A
        {
            float pv[4];
            #pragma unroll
            for (int r = 0; r < 4; r++) {
                float a = accA[r] + b1k;
                sm.x.stV[t * 5 + r] = a;
                sm.x.stE[t * 5 + r] = __expf(fminf(fmaxf(a, -8.f), 8.f));
                pv[r] = hw * a;
            }
            #pragma unroll
            for (int r = 0; r < 4; r++) {
                float v = pv[r];
                #pragma unroll
                for (int s = 16; s > 0; s >>= 1)
                    v += __shfl_down_sync(0xffffffffu, v, s);
                if (lid == 0) sm.x.redR[wid][r] = v;
            }
            __syncthreads();
            #pragma unroll
            for (int p = 0; p < 4; p++) {
                int idx = p * 256 + t;
                int k = idx >> 2, j = idx & 3;
                g_Ah [k * NN + j0 + j] = __float2half(sm.x.stV[k * 5 + j]);
                g_EAh[k * NN + j0 + j] = __float2half(sm.x.stE[k * 5 + j]);
            }
            if (t < 4) {
                float s = 0.f;
                #pragma unroll
                for (int w2i = 0; w2i < 8; w2i++) s += sm.x.redR[w2i][t];
                g_P[j0 + t] = s;
            }
            __syncthreads();
        }

        // round B
        {
            float pv[4];
            #pragma unroll
            for (int r = 0; r < 4; r++) {
                float b = accB[r];
                sm.x.stV[t * 5 + r] = b;
                sm.x.stE[t * 5 + r] = __expf(fminf(fmaxf(b, -8.f), 8.f));
                pv[r] = hw * b;
            }
            #pragma unroll
            for (int r = 0; r < 4; r++) {
                float v = pv[r];
                #pragma unroll
                for (int s = 16; s > 0; s >>= 1)
                    v += __shfl_down_sync(0xffffffffu, v, s);
                if (lid == 0) sm.x.redR[wid][r] = v;
            }
            __syncthreads();
            #pragma unroll
            for (int p = 0; p < 4; p++) {
                int idx = p * 256 + t;
                int k = idx >> 2, j = idx & 3;
                __half hb = __float2half(sm.x.stV[k * 5 + j]);
                __half he = __float2half(sm.x.stE[k * 5 + j]);
                g_Bdh [k * NN + j0 + j] = __halves2half2(hb, hb);
                g_EBdh[k * NN + j0 + j] = __halves2half2(he, he);
            }
            if (t < 4) {
                float s = 0.f;
                #pragma unroll
                for (int w2i = 0; w2i < 8; w2i++) s += sm.x.redR[w2i][t];
                g_Q[j0 + t] = s;
            }
        }
        __syncthreads();
    }

    // ======================= GRID BARRIER =======================
    __threadfence();                         // publish g_* writes
    if (t == 0) {
        unsigned old = atomicAdd(&g_bar, 1u);
        unsigned gen = old >> 8;             // / 256 CTAs
        if ((old & 255u) == 255u)
            atomicExch(&g_flag, gen + 1u);   // release this generation
        while (*(volatile unsigned*)&g_flag < gen + 1u) { }
    }
    __syncthreads();
    __threadfence();                         // acquire + L1 refresh (CCTL.IVALL)

    // ======================= PHASE 2: main =======================
    {
        const int tx = t & 15;    // j quad
        const int ty = t >> 4;    // i quad
        const int j0 = blockIdx.x * 64;
        const int i0 = blockIdx.y * 64;

        const uint2* Ah2  = reinterpret_cast<const uint2*>(g_Ah);
        const uint2* EAh2 = reinterpret_cast<const uint2*>(g_EAh);
        const uint4* Bd4  = reinterpret_cast<const uint4*>(g_Bdh);
        const uint4* EBd4 = reinterpret_cast<const uint4*>(g_EBdh);
        const uint2* Wh2  = reinterpret_cast<const uint2*>(g_wh);

        const int ar = t >> 4, ac = t & 15;
        const int gja = ar * (NN / 4) + (j0 >> 2) + ac;
        const int gib = ar * (NN / 4) + (i0 >> 2) + ac;

        float accF[4][4];
        #pragma unroll
        for (int i = 0; i < 4; i++)
            #pragma unroll
            for (int j = 0; j < 4; j++) accF[i][j] = 0.f;

        // prefetch chunk 0
        uint2 pa, pea, pw;
        uint4 pb, peb;
        pa  = Ah2 [gja];
        pea = EAh2[gja];
        pb  = Bd4 [gib];
        peb = EBd4[gib];
        if (t < 16) pw = Wh2[t];

        int buf = 0;
        for (int c = 0; c < 16; c++) {
            // store chunk c (buf last read 2 chunks ago -> safe without wait)
            sm.m.a  [buf][ar][ac] = pa;
            sm.m.ea [buf][ar][ac] = pea;
            sm.m.bd [buf][ar][ac] = pb;
            sm.m.ebd[buf][ar][ac] = peb;
            if (t < 16) sm.m.w[buf][t] = pw;
            __syncthreads();

            // prefetch chunk c+1 (latency hidden by compute below)
            if (c < 15) {
                int oa = (c + 1) * 16 * (NN / 4);
                pa  = Ah2 [gja + oa];
                pea = EAh2[gja + oa];
                pb  = Bd4 [gib + oa];
                peb = EBd4[gib + oa];
                if (t < 16) pw = Wh2[(c + 1) * 16 + t];
            }

            #pragma unroll
            for (int h = 0; h < 2; h++) {
                __half2 acc[4][2];
                #pragma unroll
                for (int i = 0; i < 4; i++)
                    #pragma unroll
                    for (int jp = 0; jp < 2; jp++)
                        acc[i][jp] = __float2half2_rn(0.f);

                #pragma unroll
                for (int k8 = 0; k8 < 8; k8++) {
                    const int kk = h * 8 + k8;
                    uint2 ua  = sm.m.a  [buf][kk][tx];
                    uint2 uea = sm.m.ea [buf][kk][tx];
                    uint4 ub  = sm.m.bd [buf][kk][ty];
                    uint4 ueb = sm.m.ebd[buf][kk][ty];
                    uint2 uw  = sm.m.w  [buf][kk];

                    unsigned au [2] = {ua.x, ua.y};
                    unsigned eau[2] = {uea.x, uea.y};
                    unsigned bu [4] = {ub.x, ub.y, ub.z, ub.w};
                    unsigned ebu[4] = {ueb.x, ueb.y, ueb.z, ueb.w};
                    __half2 hw2 = *reinterpret_cast<__half2*>(&uw.x);
                    __half2 aw2 = *reinterpret_cast<__half2*>(&uw.y);

                    #pragma unroll
                    for (int i = 0; i < 4; i++) {
                        #pragma unroll
                        for (int jp = 0; jp < 2; jp++) {
                            __half2 v = __hadd2(*reinterpret_cast<__half2*>(&au[jp]),
                                                *reinterpret_cast<__half2*>(&bu[i]));
                            unsigned vu = *reinterpret_cast<unsigned*>(&v) & 0x7FFF7FFFu;
                            __half2 av = *reinterpret_cast<__half2*>(&vu);
                            acc[i][jp] = __hfma2(av, hw2, acc[i][jp]);
                            __half2 e = __hmul2_sat(*reinterpret_cast<__half2*>(&eau[jp]),
                                                    *reinterpret_cast<__half2*>(&ebu[i]));
                            acc[i][jp] = __hfma2(e, aw2, acc[i][jp]);
                        }
                    }
                }

                // flush fp16 partials to fp32 (every 8 k)
                #pragma unroll
                for (int i = 0; i < 4; i++) {
                    #pragma unroll
                    for (int jp = 0; jp < 2; jp++) {
                        float2 f = __half22float2(acc[i][jp]);
                        accF[i][2 * jp]     += f.x;
                        accF[i][2 * jp + 1] += f.y;
                    }
                }
            }
            buf ^= 1;
        }

        // epilogue: + P[j] + Q[i] + c0, hard_sigmoid
        const float c0 = g_c0;
        float4 Pv = *reinterpret_cast<const float4*>(&g_P[j0 + tx * 4]);
        #pragma unroll
        for (int i = 0; i < 4; i++) {
            int   irow = i0 + ty * 4 + i;
            float base = g_Q[irow] + c0 + 3.0f;
            float4 o;
            o.x = fminf(fmaxf(accF[i][0] + Pv.x + base, 0.f), 6.f) * (1.f / 6.f);
            o.y = fminf(fmaxf(accF[i][1] + Pv.y + base, 0.f), 6.f) * (1.f / 6.f);
            o.z = fminf(fmaxf(accF[i][2] + Pv.z + base, 0.f), 6.f) * (1.f / 6.f);
            o.w = fminf(fmaxf(accF[i][3] + Pv.w + base, 0.f), 6.f) * (1.f / 6.f);
            *reinterpret_cast<float4*>(&out[irow * NN + j0 + tx * 4]) = o;
        }
    }
}

// ---------------------------------------------------------------------------
extern "C" void kernel_launch(void* const* d_in, const int* in_sizes, int n_in,
                              void* d_out, int out_size) {
    const float* x     = (const float*)d_in[0];
    const float* W_enc = (const float*)d_in[1];
    const float* b_enc = (const float*)d_in[2];
    const float* W1    = (const float*)d_in[3];
    const float* b1    = (const float*)d_in[4];
    const float* W2    = (const float*)d_in[5];
    const float* b2    = (const float*)d_in[6];
    float* out = (float*)d_out;

    dim3 grid(16, 16);
    fused_kernel<<<grid, 256>>>(x, W_enc, b_enc, W1, b1, W2, b2, out);
}

// round 16
// speedup vs baseline: 1.0116x; 1.0005x over previous
#include <cuda_runtime.h>
#include <cuda_fp16.h>

#define NN  1024
#define RAW 128
#define DD  128
#define HH  256

#define SELU_ALPHA 1.6732632423543772f
#define SELU_SCALE 1.0507009873554805f

// Scratch (static __device__ arrays; no allocation)
__device__ __half  g_Ah  [HH * NN];   // A^T fp16                 [k][j]
__device__ __half  g_EAh [HH * NN];   // exp(A^T) fp16            [k][j]
__device__ __half2 g_Bdh [HH * NN];   // {B,B} dup fp16           [k][i]
__device__ __half2 g_EBdh[HH * NN];   // {expB,expB} dup fp16     [k][i]
__device__ float   g_P   [NN];        // P[j] = sum_k hw_k A[k][j]
__device__ float   g_Q   [NN];        // Q[i] = sum_k hw_k B[k][i]
__device__ __half2 g_wh  [HH * 2];    // [k][0]={hw,hw} [k][1]={asw,asw}
__device__ float   g_c0;              // b2 - sum asw

// Grid barrier state (monotonic; replay-safe, never reset)
__device__ unsigned g_bar;
__device__ unsigned g_flag;

// Shared-memory overlay for the two phases
struct AuxSmem {
    float sx [4][RAW];
    float sz [4][DD];
    float swa[16 * 256];
    float swb[16 * 256];
    float stV[HH * 5];
    float stE[HH * 5];
    float redR[8][4];
};
struct MainSmem {
    uint2 a  [2][16][16];   // [buf][k][j4]  4 halves
    uint2 ea [2][16][16];
    uint4 bd [2][16][16];   // [buf][k][i4]  4 dup half2
    uint4 ebd[2][16][16];
    uint2 w  [2][16];       // {hw2, aw2}
};
union USmem { AuxSmem x; MainSmem m; };

// ---------------------------------------------------------------------------
// Fused kernel.  Grid (16,16) x 256 threads, occupancy 2 (all CTAs resident).
// Phase 1 (aux): CTA bid handles j rows [bid*4, bid*4+4).
// Phase 2 (main): 64x64 output tile with fp16x2 core.
// ---------------------------------------------------------------------------
__global__ __launch_bounds__(256, 2) void fused_kernel(
        const float* __restrict__ x,     const float* __restrict__ W_enc,
        const float* __restrict__ b_enc, const float* __restrict__ W1,
        const float* __restrict__ b1,    const float* __restrict__ W2,
        const float* __restrict__ b2,    float* __restrict__ out) {
    __shared__ USmem sm;

    const int t   = threadIdx.x;
    const int bid = blockIdx.y * 16 + blockIdx.x;

    // ======================= PHASE 1: aux =======================
    {
        const int j0 = bid * 4;

        if (bid == 0) {
            float w   = W2[t];
            float sw  = SELU_SCALE * w;
            float asw = SELU_ALPHA * sw;
            float hwr = __half2float(__float2half(0.5f * sw));   // fp16-rounded
            g_wh[2 * t]     = __float2half2_rn(hwr);
            g_wh[2 * t + 1] = __float2half2_rn(asw);
            sm.x.stV[t] = asw;
            __syncthreads();
            #pragma unroll
            for (int s = 128; s > 0; s >>= 1) {
                if (t < s) sm.x.stV[t] += sm.x.stV[t + s];
                __syncthreads();
            }
            if (t == 0) g_c0 = b2[0] - sm.x.stV[0];
            __syncthreads();
        }

        #pragma unroll
        for (int s = 0; s < 2; s++) {
            int idx = t + s * 256;
            sm.x.sx[idx >> 7][idx & 127] = x[(j0 + (idx >> 7)) * RAW + (idx & 127)];
        }
        __syncthreads();

        // z = x @ W_enc + b_enc
        {
            const int k  = t & 127;
            const int rh = t >> 7;
            float za0 = 0.f, za1 = 0.f;
            for (int c0 = 0; c0 < RAW; c0 += 16) {
                const float4* src = reinterpret_cast<const float4*>(W_enc + c0 * DD);
                float4* dst = reinterpret_cast<float4*>(sm.x.swa);
                dst[t]       = src[t];
                dst[t + 256] = src[t + 256];
                __syncthreads();
                #pragma unroll
                for (int cc = 0; cc < 16; cc++) {
                    float w = sm.x.swa[cc * DD + k];
                    za0 = fmaf(sm.x.sx[2 * rh][c0 + cc],     w, za0);
                    za1 = fmaf(sm.x.sx[2 * rh + 1][c0 + cc], w, za1);
                }
                __syncthreads();
            }
            float bb = b_enc[k];
            sm.x.sz[2 * rh][k]     = za0 + bb;
            sm.x.sz[2 * rh + 1][k] = za1 + bb;
        }
        __syncthreads();

        // A = z@W1[:d]+b1 ; B = z@W1[d:]  -- weight chunks prefetched to regs
        float accA[4] = {0.f, 0.f, 0.f, 0.f};
        float accB[4] = {0.f, 0.f, 0.f, 0.f};
        {
            float4 rwa[4], rwb[4];
            {
                const float4* srcA = reinterpret_cast<const float4*>(W1);
                const float4* srcB = reinterpret_cast<const float4*>(W1 + DD * HH);
                #pragma unroll
                for (int s = 0; s < 4; s++) {
                    rwa[s] = srcA[t + s * 256];
                    rwb[s] = srcB[t + s * 256];
                }
            }
            for (int c0 = 0; c0 < DD; c0 += 16) {
                float4* dstA = reinterpret_cast<float4*>(sm.x.swa);
                float4* dstB = reinterpret_cast<float4*>(sm.x.swb);
                #pragma unroll
                for (int s = 0; s < 4; s++) {
                    dstA[t + s * 256] = rwa[s];
                    dstB[t + s * 256] = rwb[s];
                }
                __syncthreads();
                if (c0 < DD - 16) {
                    const float4* srcA = reinterpret_cast<const float4*>(W1 + (c0 + 16) * HH);
                    const float4* srcB = reinterpret_cast<const float4*>(W1 + (c0 + 16 + DD) * HH);
                    #pragma unroll
                    for (int s = 0; s < 4; s++) {
                        rwa[s] = srcA[t + s * 256];
                        rwb[s] = srcB[t + s * 256];
                    }
                }
                #pragma unroll
                for (int cc = 0; cc < 16; cc++) {
                    float wa = sm.x.swa[cc * HH + t];
                    float wb = sm.x.swb[cc * HH + t];
                    #pragma unroll
                    for (int r = 0; r < 4; r++) {
                        float zz = sm.x.sz[r][c0 + cc];
                        accA[r] = fmaf(zz, wa, accA[r]);
                        accB[r] = fmaf(zz, wb, accB[r]);
                    }
                }
                __syncthreads();
            }
        }

        const float b1k = b1[t];
        const float hw  = __half2float(__float2half(0.5f * SELU_SCALE * W2[t]));
        const int wid = t >> 5, lid = t & 31;

        // round A
        {
            float pv[4];
            #pragma unroll
            for (int r = 0; r < 4; r++) {
                float a = accA[r] + b1k;
                sm.x.stV[t * 5 + r] = a;
                sm.x.stE[t * 5 + r] = __expf(fminf(fmaxf(a, -8.f), 8.f));
                pv[r] = hw * a;
            }
            #pragma unroll
            for (int r = 0; r < 4; r++) {
                float v = pv[r];
                #pragma unroll
                for (int s = 16; s > 0; s >>= 1)
                    v += __shfl_down_sync(0xffffffffu, v, s);
                if (lid == 0) sm.x.redR[wid][r] = v;
            }
            __syncthreads();
            #pragma unroll
            for (int p = 0; p < 4; p++) {
                int idx = p * 256 + t;
                int k = idx >> 2, j = idx & 3;
                g_Ah [k * NN + j0 + j] = __float2half(sm.x.stV[k * 5 + j]);
                g_EAh[k * NN + j0 + j] = __float2half(sm.x.stE[k * 5 + j]);
            }
            if (t < 4) {
                float s = 0.f;
                #pragma unroll
                for (int w2i = 0; w2i < 8; w2i++) s += sm.x.redR[w2i][t];
                g_P[j0 + t] = s;
            }
            __syncthreads();
        }

        // round B
        {
            float pv[4];
            #pragma unroll
            for (int r = 0; r < 4; r++) {
                float b = accB[r];
                sm.x.stV[t * 5 + r] = b;
                sm.x.stE[t * 5 + r] = __expf(fminf(fmaxf(b, -8.f), 8.f));
                pv[r] = hw * b;
            }
            #pragma unroll
            for (int r = 0; r < 4; r++) {
                float v = pv[r];
                #pragma unroll
                for (int s = 16; s > 0; s >>= 1)
                    v += __shfl_down_sync(0xffffffffu, v, s);
                if (lid == 0) sm.x.redR[wid][r] = v;
            }
            __syncthreads();
            #pragma unroll
            for (int p = 0; p < 4; p++) {
                int idx = p * 256 + t;
                int k = idx >> 2, j = idx & 3;
                __half hb = __float2half(sm.x.stV[k * 5 + j]);
                __half he = __float2half(sm.x.stE[k * 5 + j]);
                g_Bdh [k * NN + j0 + j] = __halves2half2(hb, hb);
                g_EBdh[k * NN + j0 + j] = __halves2half2(he, he);
            }
            if (t < 4) {
                float s = 0.f;
                #pragma unroll
                for (int w2i = 0; w2i < 8; w2i++) s += sm.x.redR[w2i][t];
                g_Q[j0 + t] = s;
            }
        }
        __syncthreads();
    }

    // ======================= GRID BARRIER =======================
    __threadfence();                         // publish g_* writes
    if (t == 0) {
        unsigned old = atomicAdd(&g_bar, 1u);
        unsigned gen = old >> 8;             // / 256 CTAs
        if ((old & 255u) == 255u)
            atomicExch(&g_flag, gen + 1u);   // release this generation
        while (*(volatile unsigned*)&g_flag < gen + 1u) { }
    }
    __syncthreads();
    __threadfence();                         // acquire + L1 refresh

    // ======================= PHASE 2: main =======================
    {
        const int tx = t & 15;    // j quad
        const int ty = t >> 4;    // i quad
        const int j0 = blockIdx.x * 64;
        const int i0 = blockIdx.y * 64;

        const uint2* Ah2  = reinterpret_cast<const uint2*>(g_Ah);
        const uint2* EAh2 = reinterpret_cast<const uint2*>(g_EAh);
        const uint4* Bd4  = reinterpret_cast<const uint4*>(g_Bdh);
        const uint4* EBd4 = reinterpret_cast<const uint4*>(g_EBdh);
        const uint2* Wh2  = reinterpret_cast<const uint2*>(g_wh);

        const int ar = t >> 4, ac = t & 15;
        const int gja = ar * (NN / 4) + (j0 >> 2) + ac;
        const int gib = ar * (NN / 4) + (i0 >> 2) + ac;

        float accF[4][4];
        #pragma unroll
        for (int i = 0; i < 4; i++)
            #pragma unroll
            for (int j = 0; j < 4; j++) accF[i][j] = 0.f;

        // prefetch chunk 0 (global)
        uint2 pa, pea, pw;
        uint4 pb, peb;
        pa  = Ah2 [gja];
        pea = EAh2[gja];
        pb  = Bd4 [gib];
        peb = EBd4[gib];
        if (t < 16) pw = Wh2[t];

        int buf = 0;
        for (int c = 0; c < 16; c++) {
            // store chunk c (buf last read 2 chunks ago -> safe without wait)
            sm.m.a  [buf][ar][ac] = pa;
            sm.m.ea [buf][ar][ac] = pea;
            sm.m.bd [buf][ar][ac] = pb;
            sm.m.ebd[buf][ar][ac] = peb;
            if (t < 16) sm.m.w[buf][t] = pw;
            __syncthreads();

            // prefetch chunk c+1 (global; latency hidden by compute below)
            if (c < 15) {
                int oa = (c + 1) * 16 * (NN / 4);
                pa  = Ah2 [gja + oa];
                pea = EAh2[gja + oa];
                pb  = Bd4 [gib + oa];
                peb = EBd4[gib + oa];
                if (t < 16) pw = Wh2[(c + 1) * 16 + t];
            }

            // software-pipelined LDS: preload kk+1 while computing kk
            uint2 cua  = sm.m.a  [buf][0][tx];
            uint2 cuea = sm.m.ea [buf][0][tx];
            uint4 cub  = sm.m.bd [buf][0][ty];
            uint4 cueb = sm.m.ebd[buf][0][ty];
            uint2 cuw  = sm.m.w  [buf][0];

            __half2 acc[4][2];
            #pragma unroll
            for (int i = 0; i < 4; i++)
                #pragma unroll
                for (int jp = 0; jp < 2; jp++)
                    acc[i][jp] = __float2half2_rn(0.f);

            #pragma unroll
            for (int kk = 0; kk < 16; kk++) {
                uint2 nua, nuea, nuw;
                uint4 nub, nueb;
                if (kk < 15) {
                    nua  = sm.m.a  [buf][kk + 1][tx];
                    nuea = sm.m.ea [buf][kk + 1][tx];
                    nub  = sm.m.bd [buf][kk + 1][ty];
                    nueb = sm.m.ebd[buf][kk + 1][ty];
                    nuw  = sm.m.w  [buf][kk + 1];
                }

                unsigned au [2] = {cua.x, cua.y};
                unsigned eau[2] = {cuea.x, cuea.y};
                unsigned bu [4] = {cub.x, cub.y, cub.z, cub.w};
                unsigned ebu[4] = {cueb.x, cueb.y, cueb.z, cueb.w};
                __half2 hw2 = *reinterpret_cast<__half2*>(&cuw.x);
                __half2 aw2 = *reinterpret_cast<__half2*>(&cuw.y);

                #pragma unroll
                for (int i = 0; i < 4; i++) {
                    #pragma unroll
                    for (int jp = 0; jp < 2; jp++) {
                        __half2 v = __hadd2(*reinterpret_cast<__half2*>(&au[jp]),
                                            *reinterpret_cast<__half2*>(&bu[i]));
                        unsigned vu = *reinterpret_cast<unsigned*>(&v) & 0x7FFF7FFFu;
                        __half2 av = *reinterpret_cast<__half2*>(&vu);
                        acc[i][jp] = __hfma2(av, hw2, acc[i][jp]);
                        __half2 e = __hmul2_sat(*reinterpret_cast<__half2*>(&eau[jp]),
                                                *reinterpret_cast<__half2*>(&ebu[i]));
                        acc[i][jp] = __hfma2(e, aw2, acc[i][jp]);
                    }
                }

                // flush fp16 partials to fp32 every 8 k
                if (kk == 7 || kk == 15) {
                    #pragma unroll
                    for (int i = 0; i < 4; i++) {
                        #pragma unroll
                        for (int jp = 0; jp < 2; jp++) {
                            float2 f = __half22float2(acc[i][jp]);
                            accF[i][2 * jp]     += f.x;
                            accF[i][2 * jp + 1] += f.y;
                            acc[i][jp] = __float2half2_rn(0.f);
                        }
                    }
                }

                cua = nua; cuea = nuea; cub = nub; cueb = nueb; cuw = nuw;
            }
            buf ^= 1;
        }

        // epilogue: + P[j] + Q[i] + c0, hard_sigmoid
        const float c0 = g_c0;
        float4 Pv = *reinterpret_cast<const float4*>(&g_P[j0 + tx * 4]);
        #pragma unroll
        for (int i = 0; i < 4; i++) {
            int   irow = i0 + ty * 4 + i;
            float base = g_Q[irow] + c0 + 3.0f;
            float4 o;
            o.x = fminf(fmaxf(accF[i][0] + Pv.x + base, 0.f), 6.f) * (1.f / 6.f);
            o.y = fminf(fmaxf(accF[i][1] + Pv.y + base, 0.f), 6.f) * (1.f / 6.f);
            o.z = fminf(fmaxf(accF[i][2] + Pv.z + base, 0.f), 6.f) * (1.f / 6.f);
            o.w = fminf(fmaxf(accF[i][3] + Pv.w + base, 0.f), 6.f) * (1.f / 6.f);
            *reinterpret_cast<float4*>(&out[irow * NN + j0 + tx * 4]) = o;
        }
    }
}

// ---------------------------------------------------------------------------
extern "C" void kernel_launch(void* const* d_in, const int* in_sizes, int n_in,
                              void* d_out, int out_size) {
    const float* x     = (const float*)d_in[0];
    const float* W_enc = (const float*)d_in[1];
    const float* b_enc = (const float*)d_in[2];
    const float* W1    = (const float*)d_in[3];
    const float* b1    = (const float*)d_in[4];
    const float* W2    = (const float*)d_in[5];
    const float* b2    = (const float*)d_in[6];
    float* out = (float*)d_out;

    dim3 grid(16, 16);
    fused_kernel<<<grid, 256>>>(x, W_enc, b_enc, W1, b1, W2, b2, out);
}

// round 17
// speedup vs baseline: 1.0165x; 1.0048x over previous
#include <cuda_runtime.h>
#include <cuda_fp16.h>

#define NN  1024
#define RAW 128
#define DD  128
#define HH  256

#define SELU_ALPHA 1.6732632423543772f
#define SELU_SCALE 1.0507009873554805f

// Scratch (static __device__ arrays; no allocation)
__device__ __half  g_Ah  [HH * NN];   // A^T fp16                 [k][j]
__device__ __half  g_EAh [HH * NN];   // exp(A^T) fp16            [k][j]
__device__ __half2 g_Bdh [HH * NN];   // {B,B} dup fp16           [k][i]
__device__ __half2 g_EBdh[HH * NN];   // {expB,expB} dup fp16     [k][i]
__device__ float   g_P   [NN];        // P[j] = sum_k hw_k A[k][j]
__device__ float   g_Q   [NN];        // Q[i] = sum_k hw_k B[k][i]
__device__ __half2 g_wh  [HH * 2];    // [k][0]={hw,hw} [k][1]={asw,asw}
__device__ float   g_c0;              // b2 - sum asw

// ---------------------------------------------------------------------------
// Fused aux (R11 verbatim): prep + z + A/B GEMMs + exp + transposed fp16
// stores + P/Q.  256 blocks x 256 threads, 4 rows/blk.
// ---------------------------------------------------------------------------
__global__ __launch_bounds__(256) void aux_kernel(
        const float* __restrict__ x,     const float* __restrict__ W_enc,
        const float* __restrict__ b_enc, const float* __restrict__ W1,
        const float* __restrict__ b1,    const float* __restrict__ W2,
        const float* __restrict__ b2) {
    __shared__ float sx [4][RAW];
    __shared__ float sz [4][DD];
    __shared__ float swa[16 * 256];
    __shared__ float swb[16 * 256];
    __shared__ float stV[HH * 5];
    __shared__ float stE[HH * 5];
    __shared__ float redR[8][4];

    const int t  = threadIdx.x;          // k in [0,256)
    const int j0 = blockIdx.x * 4;

    if (blockIdx.x == 0) {
        float w   = W2[t];
        float sw  = SELU_SCALE * w;
        float asw = SELU_ALPHA * sw;
        float hwr = __half2float(__float2half(0.5f * sw));   // fp16-rounded
        g_wh[2 * t]     = __float2half2_rn(hwr);
        g_wh[2 * t + 1] = __float2half2_rn(asw);
        stV[t] = asw;
        __syncthreads();
        #pragma unroll
        for (int s = 128; s > 0; s >>= 1) {
            if (t < s) stV[t] += stV[t + s];
            __syncthreads();
        }
        if (t == 0) g_c0 = b2[0] - stV[0];
        __syncthreads();
    }

    #pragma unroll
    for (int s = 0; s < 2; s++) {
        int idx = t + s * 256;
        sx[idx >> 7][idx & 127] = x[(j0 + (idx >> 7)) * RAW + (idx & 127)];
    }
    __syncthreads();

    {
        const int k  = t & 127;
        const int rh = t >> 7;
        float za0 = 0.f, za1 = 0.f;
        for (int c0 = 0; c0 < RAW; c0 += 16) {
            const float4* src = reinterpret_cast<const float4*>(W_enc + c0 * DD);
            float4* dst = reinterpret_cast<float4*>(swa);
            dst[t]       = src[t];
            dst[t + 256] = src[t + 256];
            __syncthreads();
            #pragma unroll
            for (int cc = 0; cc < 16; cc++) {
                float w = swa[cc * DD + k];
                za0 = fmaf(sx[2 * rh][c0 + cc],     w, za0);
                za1 = fmaf(sx[2 * rh + 1][c0 + cc], w, za1);
            }
            __syncthreads();
        }
        float bb = b_enc[k];
        sz[2 * rh][k]     = za0 + bb;
        sz[2 * rh + 1][k] = za1 + bb;
    }
    __syncthreads();

    float accA[4] = {0.f, 0.f, 0.f, 0.f};
    float accB[4] = {0.f, 0.f, 0.f, 0.f};
    {
        float4 rwa[4], rwb[4];
        {
            const float4* srcA = reinterpret_cast<const float4*>(W1);
            const float4* srcB = reinterpret_cast<const float4*>(W1 + DD * HH);
            #pragma unroll
            for (int s = 0; s < 4; s++) {
                rwa[s] = srcA[t + s * 256];
                rwb[s] = srcB[t + s * 256];
            }
        }
        for (int c0 = 0; c0 < DD; c0 += 16) {
            float4* dstA = reinterpret_cast<float4*>(swa);
            float4* dstB = reinterpret_cast<float4*>(swb);
            #pragma unroll
            for (int s = 0; s < 4; s++) {
                dstA[t + s * 256] = rwa[s];
                dstB[t + s * 256] = rwb[s];
            }
            __syncthreads();
            if (c0 < DD - 16) {
                const float4* srcA = reinterpret_cast<const float4*>(W1 + (c0 + 16) * HH);
                const float4* srcB = reinterpret_cast<const float4*>(W1 + (c0 + 16 + DD) * HH);
                #pragma unroll
                for (int s = 0; s < 4; s++) {
                    rwa[s] = srcA[t + s * 256];
                    rwb[s] = srcB[t + s * 256];
                }
            }
            #pragma unroll
            for (int cc = 0; cc < 16; cc++) {
                float wa = swa[cc * HH + t];
                float wb = swb[cc * HH + t];
                #pragma unroll
                for (int r = 0; r < 4; r++) {
                    float zz = sz[r][c0 + cc];
                    accA[r] = fmaf(zz, wa, accA[r]);
                    accB[r] = fmaf(zz, wb, accB[r]);
                }
            }
            __syncthreads();
        }
    }

    const float b1k = b1[t];
    const float hw  = __half2float(__float2half(0.5f * SELU_SCALE * W2[t]));
    const int wid = t >> 5, lid = t & 31;

    // round A
    {
        float pv[4];
        #pragma unroll
        for (int r = 0; r < 4; r++) {
            float a = accA[r] + b1k;
            stV[t * 5 + r] = a;
            stE[t * 5 + r] = __expf(fminf(fmaxf(a, -8.f), 8.f));
            pv[r] = hw * a;
        }
        #pragma unroll
        for (int r = 0; r < 4; r++) {
            float v = pv[r];
            #pragma unroll
            for (int s = 16; s > 0; s >>= 1)
                v += __shfl_down_sync(0xffffffffu, v, s);
            if (lid == 0) redR[wid][r] = v;
        }
        __syncthreads();
        #pragma unroll
        for (int p = 0; p < 4; p++) {
            int idx = p * 256 + t;
            int k = idx >> 2, j = idx & 3;
            g_Ah [k * NN + j0 + j] = __float2half(stV[k * 5 + j]);
            g_EAh[k * NN + j0 + j] = __float2half(stE[k * 5 + j]);
        }
        if (t < 4) {
            float s = 0.f;
            #pragma unroll
            for (int w2i = 0; w2i < 8; w2i++) s += redR[w2i][t];
            g_P[j0 + t] = s;
        }
        __syncthreads();
    }

    // round B
    {
        float pv[4];
        #pragma unroll
        for (int r = 0; r < 4; r++) {
            float b = accB[r];
            stV[t * 5 + r] = b;
            stE[t * 5 + r] = __expf(fminf(fmaxf(b, -8.f), 8.f));
            pv[r] = hw * b;
        }
        #pragma unroll
        for (int r = 0; r < 4; r++) {
            float v = pv[r];
            #pragma unroll
            for (int s = 16; s > 0; s >>= 1)
                v += __shfl_down_sync(0xffffffffu, v, s);
            if (lid == 0) redR[wid][r] = v;
        }
        __syncthreads();
        #pragma unroll
        for (int p = 0; p < 4; p++) {
            int idx = p * 256 + t;
            int k = idx >> 2, j = idx & 3;
            __half hb = __float2half(stV[k * 5 + j]);
            __half he = __float2half(stE[k * 5 + j]);
            g_Bdh [k * NN + j0 + j] = __halves2half2(hb, hb);
            g_EBdh[k * NN + j0 + j] = __halves2half2(he, he);
        }
        if (t < 4) {
            float s = 0.f;
            #pragma unroll
            for (int w2i = 0; w2i < 8; w2i++) s += redR[w2i][t];
            g_Q[j0 + t] = s;
        }
    }
}

// ---------------------------------------------------------------------------
// Main: o[i,j] = hsig( P[j] + Q[i] + c0 + sum_k [ hw_k*|v| + asw_k*sat(e) ] )
// 64x64 tiles, 512 threads (4j x 2i per thread -> 32 warps/SM at occ 2).
// Double-buffered smem, 1 __syncthreads per 16-k chunk, split loaders
// (t<256: A/EA, t>=256: Bdup/EBdup).  fp16x2 core, flush to fp32 every 8 k.
// ---------------------------------------------------------------------------
__global__ __launch_bounds__(512, 2) void main_kernel(float* __restrict__ out) {
    __shared__ uint2 s_a  [2][16][16];   // [buf][k][j4]  4 halves
    __shared__ uint2 s_ea [2][16][16];
    __shared__ uint4 s_bd [2][16][16];   // [buf][k][i4]  4 dup half2
    __shared__ uint4 s_ebd[2][16][16];
    __shared__ uint2 s_w  [2][16];       // {hw2, aw2}

    const int t   = threadIdx.x;
    const int tx  = t & 15;    // j quad
    const int tyi = t >> 4;    // i pair (0..31): i = i0 + tyi*2 + {0,1}
    const int j0  = blockIdx.x * 64;
    const int i0  = blockIdx.y * 64;

    const uint2* Ah2  = reinterpret_cast<const uint2*>(g_Ah);
    const uint2* EAh2 = reinterpret_cast<const uint2*>(g_EAh);
    const uint4* Bd4  = reinterpret_cast<const uint4*>(g_Bdh);
    const uint4* EBd4 = reinterpret_cast<const uint4*>(g_EBdh);
    const uint2* Wh2  = reinterpret_cast<const uint2*>(g_wh);

    // split loader coords (256 entries per array, half the block each)
    const int lt = t & 255;
    const int ar = lt >> 4, ac = lt & 15;
    const bool isA = (t < 256);
    const int gja = ar * (NN / 4) + (j0 >> 2) + ac;
    const int gib = ar * (NN / 4) + (i0 >> 2) + ac;

    float accF[2][4];
    #pragma unroll
    for (int i = 0; i < 2; i++)
        #pragma unroll
        for (int j = 0; j < 4; j++) accF[i][j] = 0.f;

    // prefetch chunk 0
    uint2 pa, pea, pw;
    uint4 pb, peb;
    if (isA) {
        pa  = Ah2 [gja];
        pea = EAh2[gja];
    } else {
        pb  = Bd4 [gib];
        peb = EBd4[gib];
    }
    if (t < 16) pw = Wh2[t];

    int buf = 0;
    for (int c = 0; c < 16; c++) {
        // store chunk c (buf last read 2 chunks ago -> safe without wait)
        if (isA) {
            s_a [buf][ar][ac] = pa;
            s_ea[buf][ar][ac] = pea;
        } else {
            s_bd [buf][ar][ac] = pb;
            s_ebd[buf][ar][ac] = peb;
        }
        if (t < 16) s_w[buf][t] = pw;
        __syncthreads();

        // prefetch chunk c+1
        if (c < 15) {
            int oa = (c + 1) * 16 * (NN / 4);
            if (isA) {
                pa  = Ah2 [gja + oa];
                pea = EAh2[gja + oa];
            } else {
                pb  = Bd4 [gib + oa];
                peb = EBd4[gib + oa];
            }
            if (t < 16) pw = Wh2[(c + 1) * 16 + t];
        }

        #pragma unroll
        for (int h = 0; h < 2; h++) {
            __half2 acc[2][2];
            #pragma unroll
            for (int i = 0; i < 2; i++)
                #pragma unroll
                for (int jp = 0; jp < 2; jp++)
                    acc[i][jp] = __float2half2_rn(0.f);

            #pragma unroll
            for (int k8 = 0; k8 < 8; k8++) {
                const int kk = h * 8 + k8;
                uint2 ua  = s_a [buf][kk][tx];
                uint2 uea = s_ea[buf][kk][tx];
                // 2 dup half2 for this thread's i-pair
                uint2 ub  = reinterpret_cast<const uint2*>(&s_bd [buf][kk][0])[tyi];
                uint2 ueb = reinterpret_cast<const uint2*>(&s_ebd[buf][kk][0])[tyi];
                uint2 uw  = s_w[buf][kk];

                unsigned au [2] = {ua.x, ua.y};
                unsigned eau[2] = {uea.x, uea.y};
                unsigned bu [2] = {ub.x, ub.y};
                unsigned ebu[2] = {ueb.x, ueb.y};
                __half2 hw2 = *reinterpret_cast<__half2*>(&uw.x);
                __half2 aw2 = *reinterpret_cast<__half2*>(&uw.y);

                #pragma unroll
                for (int i = 0; i < 2; i++) {
                    #pragma unroll
                    for (int jp = 0; jp < 2; jp++) {
                        __half2 v = __hadd2(*reinterpret_cast<__half2*>(&au[jp]),
                                            *reinterpret_cast<__half2*>(&bu[i]));
                        unsigned vu = *reinterpret_cast<unsigned*>(&v) & 0x7FFF7FFFu;
                        __half2 av = *reinterpret_cast<__half2*>(&vu);
                        acc[i][jp] = __hfma2(av, hw2, acc[i][jp]);
                        __half2 e = __hmul2_sat(*reinterpret_cast<__half2*>(&eau[jp]),
                                                *reinterpret_cast<__half2*>(&ebu[i]));
                        acc[i][jp] = __hfma2(e, aw2, acc[i][jp]);
                    }
                }
            }

            // flush fp16 partials to fp32 (every 8 k)
            #pragma unroll
            for (int i = 0; i < 2; i++) {
                #pragma unroll
                for (int jp = 0; jp < 2; jp++) {
                    float2 f = __half22float2(acc[i][jp]);
                    accF[i][2 * jp]     += f.x;
                    accF[i][2 * jp + 1] += f.y;
                }
            }
        }
        buf ^= 1;
    }

    // epilogue: + P[j] + Q[i] + c0, hard_sigmoid
    const float c0 = g_c0;
    float4 Pv = *reinterpret_cast<const float4*>(&g_P[j0 + tx * 4]);
    #pragma unroll
    for (int i = 0; i < 2; i++) {
        int   irow = i0 + tyi * 2 + i;
        float base = g_Q[irow] + c0 + 3.0f;
        float4 o;
        o.x = fminf(fmaxf(accF[i][0] + Pv.x + base, 0.f), 6.f) * (1.f / 6.f);
        o.y = fminf(fmaxf(accF[i][1] + Pv.y + base, 0.f), 6.f) * (1.f / 6.f);
        o.z = fminf(fmaxf(accF[i][2] + Pv.z + base, 0.f), 6.f) * (1.f / 6.f);
        o.w = fminf(fmaxf(accF[i][3] + Pv.w + base, 0.f), 6.f) * (1.f / 6.f);
        *reinterpret_cast<float4*>(&out[irow * NN + j0 + tx * 4]) = o;
    }
}

// ---------------------------------------------------------------------------
extern "C" void kernel_launch(void* const* d_in, const int* in_sizes, int n_in,
                              void* d_out, int out_size) {
    const float* x     = (const float*)d_in[0];
    const float* W_enc = (const float*)d_in[1];
    const float* b_enc = (const float*)d_in[2];
    const float* W1    = (const float*)d_in[3];
    const float* b1    = (const float*)d_in[4];
    const float* W2    = (const float*)d_in[5];
    const float* b2    = (const float*)d_in[6];
    float* out = (float*)d_out;

    aux_kernel<<<NN / 4, 256>>>(x, W_enc, b_enc, W1, b1, W2, b2);

    dim3 grid(NN / 64, NN / 64);
    main_kernel<<<grid, 512>>>(out);
}